// round 1
// baseline (speedup 1.0000x reference)
#include <cuda_runtime.h>

// Shapes fixed by the problem
#define BB  256
#define DD  768
#define NRR 4096   // Nr == Ni
#define AA  8192

__device__ __constant__ float kINV_TEMP = 20.0f;   // 1/0.05
__device__ __constant__ float kMOM      = 0.2f;

// Scratch (device globals: no allocs allowed)
__device__ float g_xnorm[BB * DD];
__device__ float g_logits[(long)BB * AA];
__device__ float g_pall[(long)BB * AA];
__device__ float g_stats[BB * 4];      // max_rgb, sum_rgb, max_ir, sum_ir
__device__ int   g_rowidx[BB];

// ---------------------------------------------------------------- init
__global__ void k_init(float* d_out) {
    long idx = (long)blockIdx.x * blockDim.x + threadIdx.x;
    long stride = (long)gridDim.x * blockDim.x;
    long total = (long)BB * AA;
    for (long i = idx; i < total; i += stride) g_pall[i] = 0.0f;
    if (idx < 2)  d_out[idx] = 0.0f;
    if (idx < BB) g_rowidx[idx] = -1;
}

// ---------------------------------------------------------------- x rownorm
__global__ void k_xnorm(const float* __restrict__ x) {
    int b = blockIdx.x, t = threadIdx.x;
    __shared__ float red[256];
    float v0 = x[b * DD + t * 3 + 0];
    float v1 = x[b * DD + t * 3 + 1];
    float v2 = x[b * DD + t * 3 + 2];
    red[t] = v0 * v0 + v1 * v1 + v2 * v2;
    __syncthreads();
    for (int o = 128; o > 0; o >>= 1) {
        if (t < o) red[t] += red[t + o];
        __syncthreads();
    }
    float inv = rsqrtf(red[0]);
    g_xnorm[b * DD + t * 3 + 0] = v0 * inv;
    g_xnorm[b * DD + t * 3 + 1] = v1 * inv;
    g_xnorm[b * DD + t * 3 + 2] = v2 * inv;
}

// ---------------------------------------------------------------- rowidx: find j with pids_ir[j]==targets[i]
__global__ void k_rowidx(const int* __restrict__ targets, const int* __restrict__ pids_ir) {
    int i = blockIdx.x, t = threadIdx.x;
    int tg = targets[i];
    for (int j = t; j < NRR; j += 256)
        if (pids_ir[j] == tg) g_rowidx[i] = j;   // at most one match
}

// ---------------------------------------------------------------- GEMM: logits[b][j] = x.F^T * 20
// 64x64 tile, BK=32, 256 threads, 4x4 micro-tile
__global__ void k_gemm(const float* __restrict__ Frgb, const float* __restrict__ Fir) {
    __shared__ float Xs[64][33];
    __shared__ float Fs[64][33];
    int tid = threadIdx.x;
    int jbase = blockIdx.x * 64;
    int mbase = blockIdx.y * 64;
    const float* F = (jbase < NRR) ? (Frgb + (long)jbase * DD)
                                   : (Fir + (long)(jbase - NRR) * DD);
    const float* X = g_xnorm + (long)mbase * DD;

    float acc[4][4] = {};
    int tr = tid >> 4, tc = tid & 15;

    for (int k0 = 0; k0 < DD; k0 += 32) {
#pragma unroll
        for (int p = 0; p < 2; p++) {
            int idx = tid + p * 256;         // 0..511
            int r = idx >> 3;
            int c = (idx & 7) * 4;
            float4 xv = *(const float4*)(X + (long)r * DD + k0 + c);
            Xs[r][c] = xv.x; Xs[r][c + 1] = xv.y; Xs[r][c + 2] = xv.z; Xs[r][c + 3] = xv.w;
            float4 fv = *(const float4*)(F + (long)r * DD + k0 + c);
            Fs[r][c] = fv.x; Fs[r][c + 1] = fv.y; Fs[r][c + 2] = fv.z; Fs[r][c + 3] = fv.w;
        }
        __syncthreads();
#pragma unroll
        for (int kk = 0; kk < 32; kk++) {
            float xr[4], fr[4];
#pragma unroll
            for (int i = 0; i < 4; i++) xr[i] = Xs[tr * 4 + i][kk];
#pragma unroll
            for (int j = 0; j < 4; j++) fr[j] = Fs[tc * 4 + j][kk];
#pragma unroll
            for (int i = 0; i < 4; i++)
#pragma unroll
                for (int j = 0; j < 4; j++)
                    acc[i][j] += xr[i] * fr[j];
        }
        __syncthreads();
    }
#pragma unroll
    for (int i = 0; i < 4; i++)
#pragma unroll
        for (int j = 0; j < 4; j++)
            g_logits[(long)(mbase + tr * 4 + i) * AA + jbase + tc * 4 + j] =
                acc[i][j] * kINV_TEMP;
}

// ---------------------------------------------------------------- per-row softmax stats + loss_yc
__global__ void k_stats(const float* __restrict__ CT, const int* __restrict__ pids_rgb,
                        float* d_out) {
    int b = blockIdx.x, t = threadIdx.x;
    const float* L = g_logits + (long)b * AA;
    __shared__ float red[256];

    float mr = -1e30f, mi = -1e30f;
    for (int j = t; j < NRR; j += 256) {
        mr = fmaxf(mr, L[j]);
        mi = fmaxf(mi, L[j + NRR]);
    }
    red[t] = mr; __syncthreads();
    for (int o = 128; o > 0; o >>= 1) { if (t < o) red[t] = fmaxf(red[t], red[t + o]); __syncthreads(); }
    mr = red[0]; __syncthreads();
    red[t] = mi; __syncthreads();
    for (int o = 128; o > 0; o >>= 1) { if (t < o) red[t] = fmaxf(red[t], red[t + o]); __syncthreads(); }
    mi = red[0]; __syncthreads();

    float er = 0.f, ei = 0.f, dot = 0.f, cs = 0.f;
    for (int j = t; j < NRR; j += 256) {
        float lr = L[j];
        er += __expf(lr - mr);
        ei += __expf(L[j + NRR] - mi);
        float ct = CT[(long)b * AA + pids_rgb[j]];
        dot += ct * lr;
        cs  += ct;
    }
    // four block reductions
    red[t] = er; __syncthreads();
    for (int o = 128; o > 0; o >>= 1) { if (t < o) red[t] += red[t + o]; __syncthreads(); }
    er = red[0]; __syncthreads();
    red[t] = ei; __syncthreads();
    for (int o = 128; o > 0; o >>= 1) { if (t < o) red[t] += red[t + o]; __syncthreads(); }
    ei = red[0]; __syncthreads();
    red[t] = dot; __syncthreads();
    for (int o = 128; o > 0; o >>= 1) { if (t < o) red[t] += red[t + o]; __syncthreads(); }
    dot = red[0]; __syncthreads();
    red[t] = cs; __syncthreads();
    for (int o = 128; o > 0; o >>= 1) { if (t < o) red[t] += red[t + o]; __syncthreads(); }
    cs = red[0];

    if (t == 0) {
        g_stats[b * 4 + 0] = mr;
        g_stats[b * 4 + 1] = er;
        g_stats[b * 4 + 2] = mi;
        g_stats[b * 4 + 3] = ei;
        float lse = mr + logf(er);
        float loss_row = cs * lse - dot;        // = -sum(ct * log_softmax)
        atomicAdd(&d_out[0], loss_row * (1.0f / BB));
    }
}

// ---------------------------------------------------------------- scatter 0.5*p into P_all
__global__ void k_scatter(const int* __restrict__ pr, const int* __restrict__ pi) {
    int b = blockIdx.x, t = threadIdx.x;
    const float* L = g_logits + (long)b * AA;
    float* P = g_pall + (long)b * AA;
    float mr = g_stats[b * 4 + 0], isr = 0.5f / g_stats[b * 4 + 1];
    float mi = g_stats[b * 4 + 2], isi = 0.5f / g_stats[b * 4 + 3];
    for (int j = t; j < NRR; j += 256) {
        atomicAdd(&P[pr[j]], __expf(L[j] - mr) * isr);
        atomicAdd(&P[pi[j]], __expf(L[j + NRR] - mi) * isi);
    }
}

// ---------------------------------------------------------------- loss_y = mean(-sum ct*log(P))
__global__ void k_lossy(const float* __restrict__ CT, float* d_out) {
    long idx = (long)blockIdx.x * 256 + threadIdx.x;
    long stride = (long)gridDim.x * 256;
    float s = 0.f;
    for (long i = idx; i < (long)BB * AA; i += stride)
        s -= CT[i] * logf(g_pall[i]);
    __shared__ float red[256];
    red[threadIdx.x] = s; __syncthreads();
    for (int o = 128; o > 0; o >>= 1) { if (threadIdx.x < o) red[threadIdx.x] += red[threadIdx.x + o]; __syncthreads(); }
    if (threadIdx.x == 0) atomicAdd(&d_out[1], red[0] * (1.0f / BB));
}

// ---------------------------------------------------------------- feature momentum update (chains)
// One block per sample; only chain-head blocks do work, replaying the whole chain.
__global__ void k_update(const float* __restrict__ CT, const int* __restrict__ targets,
                         float* __restrict__ outF) {
    int i = blockIdx.x, t = threadIdx.x;
    int tg = targets[i];
    for (int i2 = 0; i2 < i; i2++)
        if (targets[i2] == tg) return;        // not chain head
    int j = g_rowidx[i];
    if (j < 0) return;                        // target not present in pids_ir: no-op

    __shared__ float red[256];
    float* row = outF + (long)j * DD;
    float f0 = row[t * 3 + 0];
    float f1 = row[t * 3 + 1];
    float f2 = row[t * 3 + 2];

    for (int s = i; s < BB; s++) {
        if (targets[s] != tg) continue;
        float yci = CT[(long)s * AA + tg];
        float m  = kMOM / fmaxf(yci, kMOM);
        float om = 1.0f - m;
        const float* xs = g_xnorm + (long)s * DD + t * 3;
        float u0 = m * f0 + om * xs[0];
        float u1 = m * f1 + om * xs[1];
        float u2 = m * f2 + om * xs[2];
        red[t] = u0 * u0 + u1 * u1 + u2 * u2;
        __syncthreads();
        for (int o = 128; o > 0; o >>= 1) { if (t < o) red[t] += red[t + o]; __syncthreads(); }
        float inv = rsqrtf(red[0]);
        __syncthreads();
        f0 = u0 * inv; f1 = u1 * inv; f2 = u2 * inv;
    }
    row[t * 3 + 0] = f0;
    row[t * 3 + 1] = f1;
    row[t * 3 + 2] = f2;
}

// ---------------------------------------------------------------- launch
extern "C" void kernel_launch(void* const* d_in, const int* in_sizes, int n_in,
                              void* d_out, int out_size) {
    const float* inputs  = (const float*)d_in[0];
    const int*   targets = (const int*)d_in[1];
    const float* CT      = (const float*)d_in[2];
    const float* Frgb    = (const float*)d_in[3];
    const float* Fir     = (const float*)d_in[4];
    const float* Fall    = (const float*)d_in[5];
    const int*   pr      = (const int*)d_in[6];
    const int*   pi      = (const int*)d_in[7];
    float* out = (float*)d_out;

    k_init<<<2048, 256>>>(out);
    k_xnorm<<<BB, 256>>>(inputs);
    k_rowidx<<<BB, 256>>>(targets, pi);
    dim3 gg(AA / 64, BB / 64);
    k_gemm<<<gg, 256>>>(Frgb, Fir);
    k_stats<<<BB, 256>>>(CT, pr, out);
    k_scatter<<<BB, 256>>>(pr, pi);
    k_lossy<<<1024, 256>>>(CT, out);
    cudaMemcpyAsync(out + 2, Fall, (size_t)AA * DD * sizeof(float),
                    cudaMemcpyDeviceToDevice);
    k_update<<<BB, 256>>>(CT, targets, out + 2);
}

// round 2
// speedup vs baseline: 1.4855x; 1.4855x over previous
#include <cuda_runtime.h>
#include <cuda_bf16.h>
#include <cstdint>

// Shapes fixed by the problem
#define BB  256
#define DD  768
#define NRR 4096   // Nr == Ni
#define AA  8192

#define BM 128
#define BN 128
#define BKT 32
#define LDT 40     // padded smem row stride (bf16 elems): conflict-free for ldmatrix

__device__ __constant__ float kINV_TEMP = 20.0f;   // 1/0.05
__device__ __constant__ float kMOM      = 0.2f;

// Scratch (device globals: no allocs allowed)
__device__ float g_xnorm[BB * DD];
__device__ __nv_bfloat16 g_xhi[BB * DD];
__device__ __nv_bfloat16 g_xlo[BB * DD];
__device__ __nv_bfloat16 g_fhi[(long)AA * DD];
__device__ __nv_bfloat16 g_flo[(long)AA * DD];
__device__ float g_logits[(long)BB * AA];
__device__ float g_pall[(long)BB * AA];
__device__ int   g_rowidx[BB];

// ---------------------------------------------------------------- init
__global__ void k_init(float* d_out) {
    long idx = (long)blockIdx.x * blockDim.x + threadIdx.x;
    long stride = (long)gridDim.x * blockDim.x;
    long total = (long)BB * AA;
    for (long i = idx; i < total; i += stride) g_pall[i] = 0.0f;
    if (idx < 2)  d_out[idx] = 0.0f;
    if (idx < BB) g_rowidx[idx] = -1;
}

// ---------------------------------------------------------------- F fp32 -> bf16 hi/lo
__global__ void k_conv(const float* __restrict__ Frgb, const float* __restrict__ Fir) {
    const long NF = (long)NRR * DD;
    long idx = ((long)blockIdx.x * blockDim.x + threadIdx.x) * 4;
    long stride = (long)gridDim.x * blockDim.x * 4;
    for (long i = idx; i < 2 * NF; i += stride) {
        float4 v = (i < NF) ? *(const float4*)(Frgb + i)
                            : *(const float4*)(Fir + (i - NF));
        __nv_bfloat16 h[4], l[4];
        float vv[4] = {v.x, v.y, v.z, v.w};
#pragma unroll
        for (int q = 0; q < 4; q++) {
            h[q] = __float2bfloat16_rn(vv[q]);
            l[q] = __float2bfloat16_rn(vv[q] - __bfloat162float(h[q]));
        }
        *(uint2*)(g_fhi + i) = *(uint2*)h;
        *(uint2*)(g_flo + i) = *(uint2*)l;
    }
}

// ---------------------------------------------------------------- x rownorm + bf16 split
__global__ void k_xnorm(const float* __restrict__ x) {
    int b = blockIdx.x, t = threadIdx.x;
    __shared__ float red[256];
    float v0 = x[b * DD + t * 3 + 0];
    float v1 = x[b * DD + t * 3 + 1];
    float v2 = x[b * DD + t * 3 + 2];
    red[t] = v0 * v0 + v1 * v1 + v2 * v2;
    __syncthreads();
    for (int o = 128; o > 0; o >>= 1) {
        if (t < o) red[t] += red[t + o];
        __syncthreads();
    }
    float inv = rsqrtf(red[0]);
    float w[3] = {v0 * inv, v1 * inv, v2 * inv};
#pragma unroll
    for (int q = 0; q < 3; q++) {
        int off = b * DD + t * 3 + q;
        g_xnorm[off] = w[q];
        __nv_bfloat16 h = __float2bfloat16_rn(w[q]);
        g_xhi[off] = h;
        g_xlo[off] = __float2bfloat16_rn(w[q] - __bfloat162float(h));
    }
}

// ---------------------------------------------------------------- rowidx: find j with pids_ir[j]==targets[i]
__global__ void k_rowidx(const int* __restrict__ targets, const int* __restrict__ pids_ir) {
    int i = blockIdx.x, t = threadIdx.x;
    int tg = targets[i];
    for (int j = t; j < NRR; j += 256)
        if (pids_ir[j] == tg) g_rowidx[i] = j;   // at most one match
}

// ---------------------------------------------------------------- tensor-core GEMM (bf16 split)
// logits[m][n] = 20 * sum_k x[m][k]*F[n][k],  via hh + hl + lh bf16 MMAs, fp32 accum
__device__ __forceinline__ void ldmat4(uint32_t* r, const __nv_bfloat16* p) {
    uint32_t a = (uint32_t)__cvta_generic_to_shared(p);
    asm volatile("ldmatrix.sync.aligned.m8n8.x4.shared.b16 {%0,%1,%2,%3}, [%4];"
                 : "=r"(r[0]), "=r"(r[1]), "=r"(r[2]), "=r"(r[3]) : "r"(a));
}
__device__ __forceinline__ void mma16816(float* c, const uint32_t* a, const uint32_t* b) {
    asm volatile("mma.sync.aligned.m16n8k16.row.col.f32.bf16.bf16.f32 "
                 "{%0,%1,%2,%3}, {%4,%5,%6,%7}, {%8,%9}, {%0,%1,%2,%3};"
                 : "+f"(c[0]), "+f"(c[1]), "+f"(c[2]), "+f"(c[3])
                 : "r"(a[0]), "r"(a[1]), "r"(a[2]), "r"(a[3]), "r"(b[0]), "r"(b[1]));
}

__global__ void __launch_bounds__(256, 1) k_gemm_tc() {
    __shared__ __nv_bfloat16 Ah[BM * LDT], Al[BM * LDT];
    __shared__ __nv_bfloat16 Bh[BN * LDT], Bl[BN * LDT];

    int tid = threadIdx.x;
    int lane = tid & 31, warp = tid >> 5;
    int warp_m = warp >> 2, warp_n = warp & 3;     // 2 x 4 warps
    int jbase = blockIdx.x * BN;
    int mbase = blockIdx.y * BM;

    // loader coords: 4 threads per 32-elem row, 64 rows per pass, 2 passes
    int lr = tid >> 2;           // 0..63
    int lc = (tid & 3) * 8;      // 0,8,16,24

    float acc[4][4][4];
#pragma unroll
    for (int i = 0; i < 4; i++)
#pragma unroll
        for (int j = 0; j < 4; j++)
#pragma unroll
            for (int q = 0; q < 4; q++) acc[i][j][q] = 0.f;

    // frag-load address components (constant across k-loop)
    int arow = warp_m * 64 + (lane & 15);
    int acolo = (lane >> 4) * 8;
    int brow = warp_n * 32 + (lane & 7) + ((lane >> 4) << 3);
    int bcolo = ((lane >> 3) & 1) * 8;

    for (int k0 = 0; k0 < DD; k0 += BKT) {
#pragma unroll
        for (int p = 0; p < 2; p++) {
            int r = lr + p * 64;
            long ga = (long)(mbase + r) * DD + k0 + lc;
            long gb = (long)(jbase + r) * DD + k0 + lc;
            *(uint4*)&Ah[r * LDT + lc] = *(const uint4*)(g_xhi + ga);
            *(uint4*)&Al[r * LDT + lc] = *(const uint4*)(g_xlo + ga);
            *(uint4*)&Bh[r * LDT + lc] = *(const uint4*)(g_fhi + gb);
            *(uint4*)&Bl[r * LDT + lc] = *(const uint4*)(g_flo + gb);
        }
        __syncthreads();

#pragma unroll
        for (int ks = 0; ks < 2; ks++) {
            int kk = ks * 16;
            uint32_t ah[4][4], al[4][4], bh[4][2], bl[4][2];
#pragma unroll
            for (int mt = 0; mt < 4; mt++) {
                const int off = (arow + mt * 16) * LDT + kk + acolo;
                ldmat4(ah[mt], Ah + off);
                ldmat4(al[mt], Al + off);
            }
#pragma unroll
            for (int ntp = 0; ntp < 2; ntp++) {
                const int off = (brow + ntp * 16) * LDT + kk + bcolo;
                uint32_t t4[4];
                ldmat4(t4, Bh + off);
                bh[2 * ntp][0] = t4[0]; bh[2 * ntp][1] = t4[1];
                bh[2 * ntp + 1][0] = t4[2]; bh[2 * ntp + 1][1] = t4[3];
                ldmat4(t4, Bl + off);
                bl[2 * ntp][0] = t4[0]; bl[2 * ntp][1] = t4[1];
                bl[2 * ntp + 1][0] = t4[2]; bl[2 * ntp + 1][1] = t4[3];
            }
#pragma unroll
            for (int mt = 0; mt < 4; mt++)
#pragma unroll
                for (int nt = 0; nt < 4; nt++) {
                    mma16816(acc[mt][nt], ah[mt], bh[nt]);
                    mma16816(acc[mt][nt], ah[mt], bl[nt]);
                    mma16816(acc[mt][nt], al[mt], bh[nt]);
                }
        }
        __syncthreads();
    }

    // epilogue: scale by 1/TEMP, write fp32 logits
#pragma unroll
    for (int mt = 0; mt < 4; mt++)
#pragma unroll
        for (int nt = 0; nt < 4; nt++) {
            int row = mbase + warp_m * 64 + mt * 16 + (lane >> 2);
            int col = jbase + warp_n * 32 + nt * 8 + (lane & 3) * 2;
            float2 v0 = make_float2(acc[mt][nt][0] * kINV_TEMP, acc[mt][nt][1] * kINV_TEMP);
            float2 v1 = make_float2(acc[mt][nt][2] * kINV_TEMP, acc[mt][nt][3] * kINV_TEMP);
            *(float2*)(g_logits + (long)row * AA + col) = v0;
            *(float2*)(g_logits + (long)(row + 8) * AA + col) = v1;
        }
}

// ---------------------------------------------------------------- per-row softmax stats + loss_yc + scatter
__global__ void k_stats_scatter(const float* __restrict__ CT,
                                const int* __restrict__ pids_rgb,
                                const int* __restrict__ pids_ir,
                                float* d_out) {
    int b = blockIdx.x, t = threadIdx.x;
    const float* L = g_logits + (long)b * AA;
    float* P = g_pall + (long)b * AA;
    __shared__ float red[256];

    float mr = -1e30f, mi = -1e30f;
    for (int j = t; j < NRR; j += 256) {
        mr = fmaxf(mr, L[j]);
        mi = fmaxf(mi, L[j + NRR]);
    }
    red[t] = mr; __syncthreads();
    for (int o = 128; o > 0; o >>= 1) { if (t < o) red[t] = fmaxf(red[t], red[t + o]); __syncthreads(); }
    mr = red[0]; __syncthreads();
    red[t] = mi; __syncthreads();
    for (int o = 128; o > 0; o >>= 1) { if (t < o) red[t] = fmaxf(red[t], red[t + o]); __syncthreads(); }
    mi = red[0]; __syncthreads();

    float er = 0.f, ei = 0.f, dot = 0.f, cs = 0.f;
    for (int j = t; j < NRR; j += 256) {
        float lr = L[j];
        er += __expf(lr - mr);
        ei += __expf(L[j + NRR] - mi);
        float ct = CT[(long)b * AA + pids_rgb[j]];
        dot += ct * lr;
        cs  += ct;
    }
    red[t] = er; __syncthreads();
    for (int o = 128; o > 0; o >>= 1) { if (t < o) red[t] += red[t + o]; __syncthreads(); }
    er = red[0]; __syncthreads();
    red[t] = ei; __syncthreads();
    for (int o = 128; o > 0; o >>= 1) { if (t < o) red[t] += red[t + o]; __syncthreads(); }
    ei = red[0]; __syncthreads();
    red[t] = dot; __syncthreads();
    for (int o = 128; o > 0; o >>= 1) { if (t < o) red[t] += red[t + o]; __syncthreads(); }
    dot = red[0]; __syncthreads();
    red[t] = cs; __syncthreads();
    for (int o = 128; o > 0; o >>= 1) { if (t < o) red[t] += red[t + o]; __syncthreads(); }
    cs = red[0];

    if (t == 0) {
        float lse = mr + logf(er);
        float loss_row = cs * lse - dot;        // = -sum(ct * log_softmax)
        atomicAdd(&d_out[0], loss_row * (1.0f / BB));
    }

    // scatter 0.5 * softmax into P_all
    float isr = 0.5f / er, isi = 0.5f / ei;
    for (int j = t; j < NRR; j += 256) {
        atomicAdd(&P[pids_rgb[j]], __expf(L[j] - mr) * isr);
        atomicAdd(&P[pids_ir[j]],  __expf(L[j + NRR] - mi) * isi);
    }
}

// ---------------------------------------------------------------- loss_y = mean(-sum ct*log(P))
__global__ void k_lossy(const float* __restrict__ CT, float* d_out) {
    long idx = (long)blockIdx.x * 256 + threadIdx.x;
    long stride = (long)gridDim.x * 256;
    float s = 0.f;
    for (long i = idx; i < (long)BB * AA; i += stride)
        s -= CT[i] * logf(g_pall[i]);
    __shared__ float red[256];
    red[threadIdx.x] = s; __syncthreads();
    for (int o = 128; o > 0; o >>= 1) { if (threadIdx.x < o) red[threadIdx.x] += red[threadIdx.x + o]; __syncthreads(); }
    if (threadIdx.x == 0) atomicAdd(&d_out[1], red[0] * (1.0f / BB));
}

// ---------------------------------------------------------------- feature momentum update (chains)
__global__ void k_update(const float* __restrict__ CT, const int* __restrict__ targets,
                         float* __restrict__ outF) {
    int i = blockIdx.x, t = threadIdx.x;
    int tg = targets[i];
    for (int i2 = 0; i2 < i; i2++)
        if (targets[i2] == tg) return;        // not chain head
    int j = g_rowidx[i];
    if (j < 0) return;                        // target not present in pids_ir: no-op

    __shared__ float red[256];
    float* row = outF + (long)j * DD;
    float f0 = row[t * 3 + 0];
    float f1 = row[t * 3 + 1];
    float f2 = row[t * 3 + 2];

    for (int s = i; s < BB; s++) {
        if (targets[s] != tg) continue;
        float yci = CT[(long)s * AA + tg];
        float m  = kMOM / fmaxf(yci, kMOM);
        float om = 1.0f - m;
        const float* xs = g_xnorm + (long)s * DD + t * 3;
        float u0 = m * f0 + om * xs[0];
        float u1 = m * f1 + om * xs[1];
        float u2 = m * f2 + om * xs[2];
        red[t] = u0 * u0 + u1 * u1 + u2 * u2;
        __syncthreads();
        for (int o = 128; o > 0; o >>= 1) { if (t < o) red[t] += red[t + o]; __syncthreads(); }
        float inv = rsqrtf(red[0]);
        __syncthreads();
        f0 = u0 * inv; f1 = u1 * inv; f2 = u2 * inv;
    }
    row[t * 3 + 0] = f0;
    row[t * 3 + 1] = f1;
    row[t * 3 + 2] = f2;
}

// ---------------------------------------------------------------- launch
extern "C" void kernel_launch(void* const* d_in, const int* in_sizes, int n_in,
                              void* d_out, int out_size) {
    const float* inputs  = (const float*)d_in[0];
    const int*   targets = (const int*)d_in[1];
    const float* CT      = (const float*)d_in[2];
    const float* Frgb    = (const float*)d_in[3];
    const float* Fir     = (const float*)d_in[4];
    const float* Fall    = (const float*)d_in[5];
    const int*   pr      = (const int*)d_in[6];
    const int*   pi      = (const int*)d_in[7];
    float* out = (float*)d_out;

    k_init<<<2048, 256>>>(out);
    k_conv<<<2048, 256>>>(Frgb, Fir);
    k_xnorm<<<BB, 256>>>(inputs);
    k_rowidx<<<BB, 256>>>(targets, pi);
    dim3 gg(AA / BN, BB / BM);
    k_gemm_tc<<<gg, 256>>>();
    k_stats_scatter<<<BB, 256>>>(CT, pr, pi, out);
    k_lossy<<<1024, 256>>>(CT, out);
    cudaMemcpyAsync(out + 2, Fall, (size_t)AA * DD * sizeof(float),
                    cudaMemcpyDeviceToDevice);
    k_update<<<BB, 256>>>(CT, targets, out + 2);
}

// round 3
// speedup vs baseline: 2.3962x; 1.6131x over previous
#include <cuda_runtime.h>
#include <cuda_bf16.h>
#include <cstdint>

// Shapes fixed by the problem
#define BB  256
#define DD  768
#define NRR 4096   // Nr == Ni
#define AA  8192

#define BM 128
#define BN 128
#define BKT 32
#define LDT 40     // padded smem row stride (bf16 elems): conflict-free for ldmatrix

__device__ __constant__ float kINV_TEMP = 20.0f;   // 1/0.05
__device__ __constant__ float kMOM      = 0.2f;

// Scratch (device globals: no allocs allowed)
__device__ float g_xnorm[BB * DD];
__device__ __nv_bfloat16 g_xhi[BB * DD];
__device__ __nv_bfloat16 g_xlo[BB * DD];
__device__ float g_stats[BB * 6];   // per row: er, ei, dot_r, dot_i, cs, csi
__device__ int   g_inv[AA];         // pid -> row in pids_ir (or -1)

// ---------------------------------------------------------------- zero / init
__global__ void k_z() {
    int idx = blockIdx.x * 256 + threadIdx.x;
    if (idx < AA) g_inv[idx] = -1;
    if (idx < BB * 6) g_stats[idx] = 0.0f;
}

// ---------------------------------------------------------------- inverse map of pids_ir
__global__ void k_scatinv(const int* __restrict__ pids_ir) {
    int j = blockIdx.x * 256 + threadIdx.x;
    if (j < NRR) g_inv[pids_ir[j]] = j;
}

// ---------------------------------------------------------------- x rownorm + bf16 split
__global__ void k_xnorm(const float* __restrict__ x) {
    int b = blockIdx.x, t = threadIdx.x;
    __shared__ float red[256];
    float v0 = x[b * DD + t * 3 + 0];
    float v1 = x[b * DD + t * 3 + 1];
    float v2 = x[b * DD + t * 3 + 2];
    red[t] = v0 * v0 + v1 * v1 + v2 * v2;
    __syncthreads();
    for (int o = 128; o > 0; o >>= 1) {
        if (t < o) red[t] += red[t + o];
        __syncthreads();
    }
    float inv = rsqrtf(red[0]);
    float w[3] = {v0 * inv, v1 * inv, v2 * inv};
#pragma unroll
    for (int q = 0; q < 3; q++) {
        int off = b * DD + t * 3 + q;
        g_xnorm[off] = w[q];
        __nv_bfloat16 h = __float2bfloat16_rn(w[q]);
        g_xhi[off] = h;
        g_xlo[off] = __float2bfloat16_rn(w[q] - __bfloat162float(h));
    }
}

// ---------------------------------------------------------------- tensor-core GEMM + fused loss epilogue
__device__ __forceinline__ void ldmat4(uint32_t* r, const __nv_bfloat16* p) {
    uint32_t a = (uint32_t)__cvta_generic_to_shared(p);
    asm volatile("ldmatrix.sync.aligned.m8n8.x4.shared.b16 {%0,%1,%2,%3}, [%4];"
                 : "=r"(r[0]), "=r"(r[1]), "=r"(r[2]), "=r"(r[3]) : "r"(a));
}
__device__ __forceinline__ void mma16816(float* c, const uint32_t* a, const uint32_t* b) {
    asm volatile("mma.sync.aligned.m16n8k16.row.col.f32.bf16.bf16.f32 "
                 "{%0,%1,%2,%3}, {%4,%5,%6,%7}, {%8,%9}, {%0,%1,%2,%3};"
                 : "+f"(c[0]), "+f"(c[1]), "+f"(c[2]), "+f"(c[3])
                 : "r"(a[0]), "r"(a[1]), "r"(a[2]), "r"(a[3]), "r"(b[0]), "r"(b[1]));
}
__device__ __forceinline__ void split4(float4 v, uint2& hi, uint2& lo) {
    __nv_bfloat16 h[4], l[4];
    float vv[4] = {v.x, v.y, v.z, v.w};
#pragma unroll
    for (int q = 0; q < 4; q++) {
        h[q] = __float2bfloat16_rn(vv[q]);
        l[q] = __float2bfloat16_rn(vv[q] - __bfloat162float(h[q]));
    }
    hi = *(uint2*)h;
    lo = *(uint2*)l;
}

__global__ void __launch_bounds__(256, 1) k_gemm_tc(const float* __restrict__ Frgb,
                                                    const float* __restrict__ Fir,
                                                    const float* __restrict__ CT,
                                                    const int* __restrict__ pr,
                                                    const int* __restrict__ pi) {
    __shared__ __nv_bfloat16 Ah[BM * LDT], Al[BM * LDT];
    __shared__ __nv_bfloat16 Bh[BN * LDT], Bl[BN * LDT];
    __shared__ float s_e[BM], s_d[BM], s_c[BM];

    int tid = threadIdx.x;
    int lane = tid & 31, warp = tid >> 5;
    int warp_m = warp >> 2, warp_n = warp & 3;     // 2 x 4 warps
    int jbase = blockIdx.x * BN;
    int mbase = blockIdx.y * BM;
    bool is_ir = (jbase >= NRR);
    const float* F = is_ir ? (Fir + (long)(jbase - NRR) * DD)
                           : (Frgb + (long)jbase * DD);

    // loader coords
    int ar[2], ac[2];
#pragma unroll
    for (int p = 0; p < 2; p++) {
        int idx = tid * 2 + p;          // 0..511
        ar[p] = idx >> 2;               // 0..127
        ac[p] = (idx & 3) * 8;          // 0,8,16,24
    }
    int brow_ld = tid >> 1;             // 0..127
    int bcoff = (tid & 1) * 16;         // 0 or 16

    uint4 rAh[2], rAl[2];
    float4 rB[4];

    float acc[4][4][4];
#pragma unroll
    for (int i = 0; i < 4; i++)
#pragma unroll
        for (int j = 0; j < 4; j++)
#pragma unroll
            for (int q = 0; q < 4; q++) acc[i][j][q] = 0.f;

    // frag-load address components
    int arow = warp_m * 64 + (lane & 15);
    int acolo = (lane >> 4) * 8;
    int brow = warp_n * 32 + (lane & 7) + ((lane >> 4) << 3);
    int bcolo = ((lane >> 3) & 1) * 8;

    // ---- prologue: load tile 0 ----
#pragma unroll
    for (int p = 0; p < 2; p++) {
        long ga = (long)(mbase + ar[p]) * DD + ac[p];
        rAh[p] = *(const uint4*)(g_xhi + ga);
        rAl[p] = *(const uint4*)(g_xlo + ga);
    }
#pragma unroll
    for (int q = 0; q < 4; q++)
        rB[q] = *(const float4*)(F + (long)brow_ld * DD + bcoff + q * 4);
    // store tile 0
#pragma unroll
    for (int p = 0; p < 2; p++) {
        *(uint4*)&Ah[ar[p] * LDT + ac[p]] = rAh[p];
        *(uint4*)&Al[ar[p] * LDT + ac[p]] = rAl[p];
    }
#pragma unroll
    for (int q = 0; q < 4; q++) {
        uint2 hi, lo;
        split4(rB[q], hi, lo);
        *(uint2*)&Bh[brow_ld * LDT + bcoff + q * 4] = hi;
        *(uint2*)&Bl[brow_ld * LDT + bcoff + q * 4] = lo;
    }
    __syncthreads();

    for (int k0 = 0; k0 < DD; k0 += BKT) {
        bool has_next = (k0 + BKT < DD);
        if (has_next) {
            int kn = k0 + BKT;
#pragma unroll
            for (int p = 0; p < 2; p++) {
                long ga = (long)(mbase + ar[p]) * DD + kn + ac[p];
                rAh[p] = *(const uint4*)(g_xhi + ga);
                rAl[p] = *(const uint4*)(g_xlo + ga);
            }
#pragma unroll
            for (int q = 0; q < 4; q++)
                rB[q] = *(const float4*)(F + (long)brow_ld * DD + kn + bcoff + q * 4);
        }

#pragma unroll
        for (int ks = 0; ks < 2; ks++) {
            int kk = ks * 16;
            uint32_t ah[4][4], al[4][4], bh[4][2], bl[4][2];
#pragma unroll
            for (int mt = 0; mt < 4; mt++) {
                const int off = (arow + mt * 16) * LDT + kk + acolo;
                ldmat4(ah[mt], Ah + off);
                ldmat4(al[mt], Al + off);
            }
#pragma unroll
            for (int ntp = 0; ntp < 2; ntp++) {
                const int off = (brow + ntp * 16) * LDT + kk + bcolo;
                uint32_t t4[4];
                ldmat4(t4, Bh + off);
                bh[2 * ntp][0] = t4[0]; bh[2 * ntp][1] = t4[1];
                bh[2 * ntp + 1][0] = t4[2]; bh[2 * ntp + 1][1] = t4[3];
                ldmat4(t4, Bl + off);
                bl[2 * ntp][0] = t4[0]; bl[2 * ntp][1] = t4[1];
                bl[2 * ntp + 1][0] = t4[2]; bl[2 * ntp + 1][1] = t4[3];
            }
#pragma unroll
            for (int mt = 0; mt < 4; mt++)
#pragma unroll
                for (int nt = 0; nt < 4; nt++) {
                    mma16816(acc[mt][nt], ah[mt], bh[nt]);
                    mma16816(acc[mt][nt], ah[mt], bl[nt]);
                    mma16816(acc[mt][nt], al[mt], bh[nt]);
                }
        }
        __syncthreads();

        if (has_next) {
#pragma unroll
            for (int p = 0; p < 2; p++) {
                *(uint4*)&Ah[ar[p] * LDT + ac[p]] = rAh[p];
                *(uint4*)&Al[ar[p] * LDT + ac[p]] = rAl[p];
            }
#pragma unroll
            for (int q = 0; q < 4; q++) {
                uint2 hi, lo;
                split4(rB[q], hi, lo);
                *(uint2*)&Bh[brow_ld * LDT + bcoff + q * 4] = hi;
                *(uint2*)&Bl[brow_ld * LDT + bcoff + q * 4] = lo;
            }
            __syncthreads();
        }
    }

    // ---- fused epilogue: per-row Σexp(L), Σ ct*L, Σ ct (this block's modality) ----
    if (tid < BM) { s_e[tid] = 0.f; s_d[tid] = 0.f; s_c[tid] = 0.f; }
    __syncthreads();

    // pid gather for this thread's 8 columns
    const int* pidArr = is_ir ? pi : pr;
    int cbase = jbase - (is_ir ? NRR : 0);
    int pidc[8];
#pragma unroll
    for (int nt = 0; nt < 4; nt++)
#pragma unroll
        for (int q = 0; q < 2; q++)
            pidc[nt * 2 + q] = pidArr[cbase + warp_n * 32 + nt * 8 + (lane & 3) * 2 + q];

    float esum[8], dsum[8], csum[8];
#pragma unroll
    for (int i = 0; i < 8; i++) { esum[i] = 0.f; dsum[i] = 0.f; csum[i] = 0.f; }

#pragma unroll
    for (int mt = 0; mt < 4; mt++)
#pragma unroll
        for (int nt = 0; nt < 4; nt++)
#pragma unroll
            for (int q = 0; q < 4; q++) {
                int hi = q >> 1;                       // 0 or 1 (row +8)
                int ridx = mt * 2 + hi;                // local row slot
                int grow = mbase + warp_m * 64 + mt * 16 + hi * 8 + (lane >> 2);
                float L = acc[mt][nt][q] * kINV_TEMP;
                float e = __expf(L);
                float ct = CT[(long)grow * AA + pidc[nt * 2 + (q & 1)]];
                esum[ridx] += e;
                dsum[ridx] += ct * L;
                csum[ridx] += ct;
            }

    // quad reduce (lanes 0-3 share a row), then smem atomics
#pragma unroll
    for (int i = 0; i < 8; i++) {
        float e = esum[i], d = dsum[i], c = csum[i];
        e += __shfl_xor_sync(0xFFFFFFFF, e, 1); e += __shfl_xor_sync(0xFFFFFFFF, e, 2);
        d += __shfl_xor_sync(0xFFFFFFFF, d, 1); d += __shfl_xor_sync(0xFFFFFFFF, d, 2);
        c += __shfl_xor_sync(0xFFFFFFFF, c, 1); c += __shfl_xor_sync(0xFFFFFFFF, c, 2);
        if ((lane & 3) == 0) {
            int rl = warp_m * 64 + (i >> 1) * 16 + (i & 1) * 8 + (lane >> 2);
            atomicAdd(&s_e[rl], e);
            atomicAdd(&s_d[rl], d);
            atomicAdd(&s_c[rl], c);
        }
    }
    __syncthreads();

    if (tid < BM) {
        int grow = mbase + tid;
        int m = is_ir ? 1 : 0;
        atomicAdd(&g_stats[grow * 6 + 0 + m], s_e[tid]);
        atomicAdd(&g_stats[grow * 6 + 2 + m], s_d[tid]);
        atomicAdd(&g_stats[grow * 6 + 4 + m], s_c[tid]);
    }
}

// ---------------------------------------------------------------- finalize losses
__global__ void k_final(float* d_out) {
    int t = threadIdx.x;                 // row
    const float* st = g_stats + t * 6;
    float er = st[0], ei = st[1], dr = st[2], di = st[3], cs = st[4], csi = st[5];
    float lyc = cs * logf(er) - dr;
    float ly  = cs * logf(2.0f * er) + csi * logf(2.0f * ei) - dr - di;
    __shared__ float r1[256], r2[256];
    r1[t] = lyc; r2[t] = ly;
    __syncthreads();
    for (int o = 128; o > 0; o >>= 1) {
        if (t < o) { r1[t] += r1[t + o]; r2[t] += r2[t + o]; }
        __syncthreads();
    }
    if (t == 0) {
        d_out[0] = r1[0] * (1.0f / BB);
        d_out[1] = r2[0] * (1.0f / BB);
    }
}

// ---------------------------------------------------------------- feature momentum update (chains)
__global__ void k_update(const float* __restrict__ CT, const int* __restrict__ targets,
                         float* __restrict__ outF) {
    int i = blockIdx.x, t = threadIdx.x;
    int tg = targets[i];
    for (int i2 = 0; i2 < i; i2++)
        if (targets[i2] == tg) return;        // not chain head
    int j = g_inv[tg];
    if (j < 0) return;                        // target not present in pids_ir: no-op

    __shared__ float red[256];
    float* row = outF + (long)j * DD;
    float f0 = row[t * 3 + 0];
    float f1 = row[t * 3 + 1];
    float f2 = row[t * 3 + 2];

    for (int s = i; s < BB; s++) {
        if (targets[s] != tg) continue;
        float yci = CT[(long)s * AA + tg];
        float m  = kMOM / fmaxf(yci, kMOM);
        float om = 1.0f - m;
        const float* xs = g_xnorm + (long)s * DD + t * 3;
        float u0 = m * f0 + om * xs[0];
        float u1 = m * f1 + om * xs[1];
        float u2 = m * f2 + om * xs[2];
        red[t] = u0 * u0 + u1 * u1 + u2 * u2;
        __syncthreads();
        for (int o = 128; o > 0; o >>= 1) { if (t < o) red[t] += red[t + o]; __syncthreads(); }
        float inv = rsqrtf(red[0]);
        __syncthreads();
        f0 = u0 * inv; f1 = u1 * inv; f2 = u2 * inv;
    }
    row[t * 3 + 0] = f0;
    row[t * 3 + 1] = f1;
    row[t * 3 + 2] = f2;
}

// ---------------------------------------------------------------- launch
extern "C" void kernel_launch(void* const* d_in, const int* in_sizes, int n_in,
                              void* d_out, int out_size) {
    const float* inputs  = (const float*)d_in[0];
    const int*   targets = (const int*)d_in[1];
    const float* CT      = (const float*)d_in[2];
    const float* Frgb    = (const float*)d_in[3];
    const float* Fir     = (const float*)d_in[4];
    const float* Fall    = (const float*)d_in[5];
    const int*   pr      = (const int*)d_in[6];
    const int*   pi      = (const int*)d_in[7];
    float* out = (float*)d_out;

    k_z<<<32, 256>>>();
    k_xnorm<<<BB, 256>>>(inputs);
    k_scatinv<<<16, 256>>>(pi);
    dim3 gg(AA / BN, BB / BM);
    k_gemm_tc<<<gg, 256>>>(Frgb, Fir, CT, pr, pi);
    k_final<<<1, 256>>>(out);
    cudaMemcpyAsync(out + 2, Fall, (size_t)AA * DD * sizeof(float),
                    cudaMemcpyDeviceToDevice);
    k_update<<<BB, 256>>>(CT, targets, out + 2);
}

// round 4
// speedup vs baseline: 2.4528x; 1.0236x over previous
#include <cuda_runtime.h>
#include <cuda_bf16.h>
#include <cstdint>

// Shapes fixed by the problem
#define BB  256
#define DD  768
#define NRR 4096   // Nr == Ni
#define AA  8192

#define BM 128
#define BN 128
#define BKT 32
#define LDT 40     // padded smem row stride (bf16 elems): conflict-free for ldmatrix
#define STG (4 * BM * LDT)          // bf16 elems per stage (Ah,Al,Bh,Bl)
#define SMEM_BYTES (2 * STG * 2)    // 81920 bytes

__device__ __constant__ float kINV_TEMP = 20.0f;   // 1/0.05
__device__ __constant__ float kMOM      = 0.2f;

// Scratch (device globals: no allocs allowed)
__device__ float g_xnorm[BB * DD];
__device__ __nv_bfloat16 g_xhi[BB * DD];
__device__ __nv_bfloat16 g_xlo[BB * DD];
__device__ float g_stats[BB * 6];   // per row: er, ei, dot_r, dot_i, cs, csi
__device__ int   g_inv[AA];         // pid -> row in pids_ir (validated by consumer)

// ---------------------------------------------------------------- prep: xnorm + inv-map + stats zero
__global__ void k_prep(const float* __restrict__ x, const int* __restrict__ pids_ir) {
    int b = blockIdx.x, t = threadIdx.x;
    __shared__ float red[256];
    float v0 = x[b * DD + t * 3 + 0];
    float v1 = x[b * DD + t * 3 + 1];
    float v2 = x[b * DD + t * 3 + 2];
    red[t] = v0 * v0 + v1 * v1 + v2 * v2;
    __syncthreads();
    for (int o = 128; o > 0; o >>= 1) {
        if (t < o) red[t] += red[t + o];
        __syncthreads();
    }
    float inv = rsqrtf(red[0]);
    float w[3] = {v0 * inv, v1 * inv, v2 * inv};
#pragma unroll
    for (int q = 0; q < 3; q++) {
        int off = b * DD + t * 3 + q;
        g_xnorm[off] = w[q];
        __nv_bfloat16 h = __float2bfloat16_rn(w[q]);
        g_xhi[off] = h;
        g_xlo[off] = __float2bfloat16_rn(w[q] - __bfloat162float(h));
    }
    if (t < 16) {                      // 256 blocks * 16 = 4096 entries
        int j = b * 16 + t;
        g_inv[pids_ir[j]] = j;
    }
    if (t < 6) g_stats[b * 6 + t] = 0.0f;
}

// ---------------------------------------------------------------- tensor-core GEMM + fused loss epilogue
__device__ __forceinline__ void ldmat4(uint32_t* r, const __nv_bfloat16* p) {
    uint32_t a = (uint32_t)__cvta_generic_to_shared(p);
    asm volatile("ldmatrix.sync.aligned.m8n8.x4.shared.b16 {%0,%1,%2,%3}, [%4];"
                 : "=r"(r[0]), "=r"(r[1]), "=r"(r[2]), "=r"(r[3]) : "r"(a));
}
__device__ __forceinline__ void mma16816(float* c, const uint32_t* a, const uint32_t* b) {
    asm volatile("mma.sync.aligned.m16n8k16.row.col.f32.bf16.bf16.f32 "
                 "{%0,%1,%2,%3}, {%4,%5,%6,%7}, {%8,%9}, {%0,%1,%2,%3};"
                 : "+f"(c[0]), "+f"(c[1]), "+f"(c[2]), "+f"(c[3])
                 : "r"(a[0]), "r"(a[1]), "r"(a[2]), "r"(a[3]), "r"(b[0]), "r"(b[1]));
}
__device__ __forceinline__ void split4(float4 v, uint2& hi, uint2& lo) {
    __nv_bfloat16 h[4], l[4];
    float vv[4] = {v.x, v.y, v.z, v.w};
#pragma unroll
    for (int q = 0; q < 4; q++) {
        h[q] = __float2bfloat16_rn(vv[q]);
        l[q] = __float2bfloat16_rn(vv[q] - __bfloat162float(h[q]));
    }
    hi = *(uint2*)h;
    lo = *(uint2*)l;
}

__global__ void __launch_bounds__(256, 1) k_gemm_tc(const float* __restrict__ Frgb,
                                                    const float* __restrict__ Fir,
                                                    const float* __restrict__ CT,
                                                    const int* __restrict__ pr,
                                                    const int* __restrict__ pi) {
    extern __shared__ __nv_bfloat16 smp[];

    int tid = threadIdx.x;
    int lane = tid & 31, warp = tid >> 5;
    int warp_m = warp >> 2, warp_n = warp & 3;     // 2 x 4 warps
    int jbase = blockIdx.x * BN;
    int mbase = blockIdx.y * BM;
    bool is_ir = (jbase >= NRR);
    const float* F = is_ir ? (Fir + (long)(jbase - NRR) * DD)
                           : (Frgb + (long)jbase * DD);

    // loader coords
    int ar[2], ac[2];
#pragma unroll
    for (int p = 0; p < 2; p++) {
        int idx = tid * 2 + p;          // 0..511
        ar[p] = idx >> 2;               // 0..127
        ac[p] = (idx & 3) * 8;          // 0,8,16,24
    }
    int brow_ld = tid >> 1;             // 0..127
    int bcoff = (tid & 1) * 16;         // 0 or 16

    uint4 rAh[2], rAl[2];
    float4 rB[4];

    float acc[4][4][4];
#pragma unroll
    for (int i = 0; i < 4; i++)
#pragma unroll
        for (int j = 0; j < 4; j++)
#pragma unroll
            for (int q = 0; q < 4; q++) acc[i][j][q] = 0.f;

    // frag-load address components
    int arow = warp_m * 64 + (lane & 15);
    int acolo = (lane >> 4) * 8;
    int brow = warp_n * 32 + (lane & 7) + ((lane >> 4) << 3);
    int bcolo = ((lane >> 3) & 1) * 8;

    // ---- prologue: load + store tile 0 into stage 0 ----
    {
        __nv_bfloat16* Ah = smp;
        __nv_bfloat16* Al = smp + BM * LDT;
        __nv_bfloat16* Bh = smp + 2 * BM * LDT;
        __nv_bfloat16* Bl = smp + 3 * BM * LDT;
#pragma unroll
        for (int p = 0; p < 2; p++) {
            long ga = (long)(mbase + ar[p]) * DD + ac[p];
            rAh[p] = *(const uint4*)(g_xhi + ga);
            rAl[p] = *(const uint4*)(g_xlo + ga);
        }
#pragma unroll
        for (int q = 0; q < 4; q++)
            rB[q] = *(const float4*)(F + (long)brow_ld * DD + bcoff + q * 4);
#pragma unroll
        for (int p = 0; p < 2; p++) {
            *(uint4*)&Ah[ar[p] * LDT + ac[p]] = rAh[p];
            *(uint4*)&Al[ar[p] * LDT + ac[p]] = rAl[p];
        }
#pragma unroll
        for (int q = 0; q < 4; q++) {
            uint2 hi, lo;
            split4(rB[q], hi, lo);
            *(uint2*)&Bh[brow_ld * LDT + bcoff + q * 4] = hi;
            *(uint2*)&Bl[brow_ld * LDT + bcoff + q * 4] = lo;
        }
    }
    __syncthreads();

    int cur = 0;
    for (int k0 = 0; k0 < DD; k0 += BKT) {
        bool has_next = (k0 + BKT < DD);
        if (has_next) {
            int kn = k0 + BKT;
#pragma unroll
            for (int p = 0; p < 2; p++) {
                long ga = (long)(mbase + ar[p]) * DD + kn + ac[p];
                rAh[p] = *(const uint4*)(g_xhi + ga);
                rAl[p] = *(const uint4*)(g_xlo + ga);
            }
#pragma unroll
            for (int q = 0; q < 4; q++)
                rB[q] = *(const float4*)(F + (long)brow_ld * DD + kn + bcoff + q * 4);
        }

        const __nv_bfloat16* Ah = smp + cur * STG;
        const __nv_bfloat16* Al = Ah + BM * LDT;
        const __nv_bfloat16* Bh = Ah + 2 * BM * LDT;
        const __nv_bfloat16* Bl = Ah + 3 * BM * LDT;

#pragma unroll
        for (int ks = 0; ks < 2; ks++) {
            int kk = ks * 16;
            uint32_t ah[4][4], al[4][4], bh[4][2], bl[4][2];
#pragma unroll
            for (int mt = 0; mt < 4; mt++) {
                const int off = (arow + mt * 16) * LDT + kk + acolo;
                ldmat4(ah[mt], Ah + off);
                ldmat4(al[mt], Al + off);
            }
#pragma unroll
            for (int ntp = 0; ntp < 2; ntp++) {
                const int off = (brow + ntp * 16) * LDT + kk + bcolo;
                uint32_t t4[4];
                ldmat4(t4, Bh + off);
                bh[2 * ntp][0] = t4[0]; bh[2 * ntp][1] = t4[1];
                bh[2 * ntp + 1][0] = t4[2]; bh[2 * ntp + 1][1] = t4[3];
                ldmat4(t4, Bl + off);
                bl[2 * ntp][0] = t4[0]; bl[2 * ntp][1] = t4[1];
                bl[2 * ntp + 1][0] = t4[2]; bl[2 * ntp + 1][1] = t4[3];
            }
#pragma unroll
            for (int mt = 0; mt < 4; mt++)
#pragma unroll
                for (int nt = 0; nt < 4; nt++) {
                    mma16816(acc[mt][nt], ah[mt], bh[nt]);
                    mma16816(acc[mt][nt], ah[mt], bl[nt]);
                    mma16816(acc[mt][nt], al[mt], bh[nt]);
                }
        }

        if (has_next) {
            __nv_bfloat16* nAh = smp + (cur ^ 1) * STG;
            __nv_bfloat16* nAl = nAh + BM * LDT;
            __nv_bfloat16* nBh = nAh + 2 * BM * LDT;
            __nv_bfloat16* nBl = nAh + 3 * BM * LDT;
#pragma unroll
            for (int p = 0; p < 2; p++) {
                *(uint4*)&nAh[ar[p] * LDT + ac[p]] = rAh[p];
                *(uint4*)&nAl[ar[p] * LDT + ac[p]] = rAl[p];
            }
#pragma unroll
            for (int q = 0; q < 4; q++) {
                uint2 hi, lo;
                split4(rB[q], hi, lo);
                *(uint2*)&nBh[brow_ld * LDT + bcoff + q * 4] = hi;
                *(uint2*)&nBl[brow_ld * LDT + bcoff + q * 4] = lo;
            }
            __syncthreads();
            cur ^= 1;
        }
    }
    __syncthreads();   // smem reuse for epilogue

    // ---- fused epilogue: per-row Σexp(L), Σ ct*L, Σ ct (this block's modality) ----
    float* s_e = (float*)smp;
    float* s_d = s_e + BM;
    float* s_c = s_e + 2 * BM;
    if (tid < BM) { s_e[tid] = 0.f; s_d[tid] = 0.f; s_c[tid] = 0.f; }
    __syncthreads();

    const int* pidArr = is_ir ? pi : pr;
    int cbase = jbase - (is_ir ? NRR : 0);
    int pidc[8];
#pragma unroll
    for (int nt = 0; nt < 4; nt++)
#pragma unroll
        for (int q = 0; q < 2; q++)
            pidc[nt * 2 + q] = pidArr[cbase + warp_n * 32 + nt * 8 + (lane & 3) * 2 + q];

    float esum[8], dsum[8], csum[8];
#pragma unroll
    for (int i = 0; i < 8; i++) { esum[i] = 0.f; dsum[i] = 0.f; csum[i] = 0.f; }

#pragma unroll
    for (int mt = 0; mt < 4; mt++)
#pragma unroll
        for (int nt = 0; nt < 4; nt++)
#pragma unroll
            for (int q = 0; q < 4; q++) {
                int hi = q >> 1;
                int ridx = mt * 2 + hi;
                int grow = mbase + warp_m * 64 + mt * 16 + hi * 8 + (lane >> 2);
                float L = acc[mt][nt][q] * kINV_TEMP;
                float e = __expf(L);
                float ct = CT[(long)grow * AA + pidc[nt * 2 + (q & 1)]];
                esum[ridx] += e;
                dsum[ridx] += ct * L;
                csum[ridx] += ct;
            }

#pragma unroll
    for (int i = 0; i < 8; i++) {
        float e = esum[i], d = dsum[i], c = csum[i];
        e += __shfl_xor_sync(0xFFFFFFFF, e, 1); e += __shfl_xor_sync(0xFFFFFFFF, e, 2);
        d += __shfl_xor_sync(0xFFFFFFFF, d, 1); d += __shfl_xor_sync(0xFFFFFFFF, d, 2);
        c += __shfl_xor_sync(0xFFFFFFFF, c, 1); c += __shfl_xor_sync(0xFFFFFFFF, c, 2);
        if ((lane & 3) == 0) {
            int rl = warp_m * 64 + (i >> 1) * 16 + (i & 1) * 8 + (lane >> 2);
            atomicAdd(&s_e[rl], e);
            atomicAdd(&s_d[rl], d);
            atomicAdd(&s_c[rl], c);
        }
    }
    __syncthreads();

    if (tid < BM) {
        int grow = mbase + tid;
        int m = is_ir ? 1 : 0;
        atomicAdd(&g_stats[grow * 6 + 0 + m], s_e[tid]);
        atomicAdd(&g_stats[grow * 6 + 2 + m], s_d[tid]);
        atomicAdd(&g_stats[grow * 6 + 4 + m], s_c[tid]);
    }
}

// ---------------------------------------------------------------- feature update (chains) + fused loss finalize
__global__ void k_update(const float* __restrict__ CT, const int* __restrict__ targets,
                         const int* __restrict__ pids_ir,
                         float* __restrict__ outF, float* __restrict__ d_out) {
    int i = blockIdx.x, t = threadIdx.x;

    if (i == BB) {       // loss finalize block
        const float* st = g_stats + t * 6;
        float er = st[0], ei = st[1], dr = st[2], di = st[3], cs = st[4], csi = st[5];
        float lyc = cs * logf(er) - dr;
        float ly  = cs * logf(2.0f * er) + csi * logf(2.0f * ei) - dr - di;
        __shared__ float r1[256], r2[256];
        r1[t] = lyc; r2[t] = ly;
        __syncthreads();
        for (int o = 128; o > 0; o >>= 1) {
            if (t < o) { r1[t] += r1[t + o]; r2[t] += r2[t + o]; }
            __syncthreads();
        }
        if (t == 0) {
            d_out[0] = r1[0] * (1.0f / BB);
            d_out[1] = r2[0] * (1.0f / BB);
        }
        return;
    }

    int tg = targets[i];
    for (int i2 = 0; i2 < i; i2++)
        if (targets[i2] == tg) return;        // not chain head
    int j = g_inv[tg];
    if (j < 0 || j >= NRR || pids_ir[j] != tg) return;  // validated inverse map

    __shared__ float red[256];
    float* row = outF + (long)j * DD;
    float f0 = row[t * 3 + 0];
    float f1 = row[t * 3 + 1];
    float f2 = row[t * 3 + 2];

    for (int s = i; s < BB; s++) {
        if (targets[s] != tg) continue;
        float yci = CT[(long)s * AA + tg];
        float m  = kMOM / fmaxf(yci, kMOM);
        float om = 1.0f - m;
        const float* xs = g_xnorm + (long)s * DD + t * 3;
        float u0 = m * f0 + om * xs[0];
        float u1 = m * f1 + om * xs[1];
        float u2 = m * f2 + om * xs[2];
        red[t] = u0 * u0 + u1 * u1 + u2 * u2;
        __syncthreads();
        for (int o = 128; o > 0; o >>= 1) { if (t < o) red[t] += red[t + o]; __syncthreads(); }
        float inv = rsqrtf(red[0]);
        __syncthreads();
        f0 = u0 * inv; f1 = u1 * inv; f2 = u2 * inv;
    }
    row[t * 3 + 0] = f0;
    row[t * 3 + 1] = f1;
    row[t * 3 + 2] = f2;
}

// ---------------------------------------------------------------- launch
extern "C" void kernel_launch(void* const* d_in, const int* in_sizes, int n_in,
                              void* d_out, int out_size) {
    const float* inputs  = (const float*)d_in[0];
    const int*   targets = (const int*)d_in[1];
    const float* CT      = (const float*)d_in[2];
    const float* Frgb    = (const float*)d_in[3];
    const float* Fir     = (const float*)d_in[4];
    const float* Fall    = (const float*)d_in[5];
    const int*   pr      = (const int*)d_in[6];
    const int*   pi      = (const int*)d_in[7];
    float* out = (float*)d_out;

    cudaFuncSetAttribute(k_gemm_tc, cudaFuncAttributeMaxDynamicSharedMemorySize, SMEM_BYTES);

    k_prep<<<BB, 256>>>(inputs, pi);
    dim3 gg(AA / BN, BB / BM);
    k_gemm_tc<<<gg, 256, SMEM_BYTES>>>(Frgb, Fir, CT, pr, pi);
    cudaMemcpyAsync(out + 2, Fall, (size_t)AA * DD * sizeof(float),
                    cudaMemcpyDeviceToDevice);
    k_update<<<BB + 1, 256>>>(CT, targets, pi, out + 2, out);
}

// round 5
// speedup vs baseline: 2.9284x; 1.1939x over previous
#include <cuda_runtime.h>
#include <cuda_bf16.h>
#include <cstdint>

// Shapes fixed by the problem
#define BB  256
#define DD  768
#define NRR 4096   // Nr == Ni
#define AA  8192

#define BM 128
#define BN 64
#define BKT 32
#define LDT 40     // padded smem row stride (bf16 elems): conflict-free for ldmatrix
#define STG ((BM + BN) * LDT)       // bf16 elems per stage (Ah,Bh)

__device__ __constant__ float kINV_TEMP = 20.0f;   // 1/0.05
__device__ __constant__ float kMOM      = 0.2f;

// Scratch (device globals: no allocs allowed)
__device__ float g_xnorm[BB * DD];
__device__ __nv_bfloat16 g_xhi[BB * DD];
__device__ float g_stats[BB * 6];   // per row: er, ei, dot_r, dot_i, cs, csi
__device__ int   g_inv[AA];         // pid -> row in pids_ir (validated by consumer)

// ---------------------------------------------------------------- prep: xnorm + inv-map + stats zero
__global__ void k_prep(const float* __restrict__ x, const int* __restrict__ pids_ir) {
    int b = blockIdx.x, t = threadIdx.x;
    __shared__ float red[256];
    float v0 = x[b * DD + t * 3 + 0];
    float v1 = x[b * DD + t * 3 + 1];
    float v2 = x[b * DD + t * 3 + 2];
    red[t] = v0 * v0 + v1 * v1 + v2 * v2;
    __syncthreads();
    for (int o = 128; o > 0; o >>= 1) {
        if (t < o) red[t] += red[t + o];
        __syncthreads();
    }
    float inv = rsqrtf(red[0]);
    float w[3] = {v0 * inv, v1 * inv, v2 * inv};
#pragma unroll
    for (int q = 0; q < 3; q++) {
        int off = b * DD + t * 3 + q;
        g_xnorm[off] = w[q];
        g_xhi[off] = __float2bfloat16_rn(w[q]);
    }
    if (t < 16) {                      // 256 blocks * 16 = 4096 entries
        int j = b * 16 + t;
        g_inv[pids_ir[j]] = j;
    }
    if (t < 6) g_stats[b * 6 + t] = 0.0f;
}

// ---------------------------------------------------------------- tensor-core GEMM + fused loss epilogue
__device__ __forceinline__ void ldmat4(uint32_t* r, const __nv_bfloat16* p) {
    uint32_t a = (uint32_t)__cvta_generic_to_shared(p);
    asm volatile("ldmatrix.sync.aligned.m8n8.x4.shared.b16 {%0,%1,%2,%3}, [%4];"
                 : "=r"(r[0]), "=r"(r[1]), "=r"(r[2]), "=r"(r[3]) : "r"(a));
}
__device__ __forceinline__ void mma16816(float* c, const uint32_t* a, const uint32_t* b) {
    asm volatile("mma.sync.aligned.m16n8k16.row.col.f32.bf16.bf16.f32 "
                 "{%0,%1,%2,%3}, {%4,%5,%6,%7}, {%8,%9}, {%0,%1,%2,%3};"
                 : "+f"(c[0]), "+f"(c[1]), "+f"(c[2]), "+f"(c[3])
                 : "r"(a[0]), "r"(a[1]), "r"(a[2]), "r"(a[3]), "r"(b[0]), "r"(b[1]));
}
__device__ __forceinline__ uint4 cvt8(float4 a, float4 b) {
    __nv_bfloat16 h[8];
    float vv[8] = {a.x, a.y, a.z, a.w, b.x, b.y, b.z, b.w};
#pragma unroll
    for (int q = 0; q < 8; q++) h[q] = __float2bfloat16_rn(vv[q]);
    return *(uint4*)h;
}

__global__ void __launch_bounds__(256, 2) k_gemm_tc(const float* __restrict__ Frgb,
                                                    const float* __restrict__ Fir,
                                                    const float* __restrict__ CT,
                                                    const int* __restrict__ pr,
                                                    const int* __restrict__ pi) {
    __shared__ __nv_bfloat16 smp[2 * STG];

    int tid = threadIdx.x;
    int lane = tid & 31, warp = tid >> 5;
    int warp_m = warp >> 2, warp_n = warp & 3;     // 2 x 4 warps
    int jbase = blockIdx.x * BN;
    int mbase = blockIdx.y * BM;
    bool is_ir = (jbase >= NRR);
    const float* F = is_ir ? (Fir + (long)(jbase - NRR) * DD)
                           : (Frgb + (long)jbase * DD);

    // A loader coords: 2 x uint4 per thread over 128x32 tile
    int ar[2], ac[2];
#pragma unroll
    for (int p = 0; p < 2; p++) {
        int idx = tid * 2 + p;          // 0..511
        ar[p] = idx >> 2;               // 0..127
        ac[p] = (idx & 3) * 8;          // 0,8,16,24
    }
    // B loader coords: 1 x uint4 (8 bf16) per thread over 64x32 tile
    int br_ld = tid >> 2;               // 0..63
    int bc_ld = (tid & 3) * 8;          // 0,8,16,24

    uint4 rA[2];
    float4 rB0, rB1;

    float acc[4][2][4];
#pragma unroll
    for (int i = 0; i < 4; i++)
#pragma unroll
        for (int j = 0; j < 2; j++)
#pragma unroll
            for (int q = 0; q < 4; q++) acc[i][j][q] = 0.f;

    // frag-load address components
    int arow = warp_m * 64 + (lane & 15);
    int acolo = (lane >> 4) * 8;
    int brow = warp_n * 16 + (lane & 7) + ((lane >> 4) << 3);
    int bcolo = ((lane >> 3) & 1) * 8;

    // ---- prologue: load + store tile 0 into stage 0 ----
    {
        __nv_bfloat16* Ah = smp;
        __nv_bfloat16* Bh = smp + BM * LDT;
#pragma unroll
        for (int p = 0; p < 2; p++)
            rA[p] = *(const uint4*)(g_xhi + (long)(mbase + ar[p]) * DD + ac[p]);
        rB0 = *(const float4*)(F + (long)br_ld * DD + bc_ld);
        rB1 = *(const float4*)(F + (long)br_ld * DD + bc_ld + 4);
#pragma unroll
        for (int p = 0; p < 2; p++)
            *(uint4*)&Ah[ar[p] * LDT + ac[p]] = rA[p];
        *(uint4*)&Bh[br_ld * LDT + bc_ld] = cvt8(rB0, rB1);
    }
    __syncthreads();

    int cur = 0;
    for (int k0 = 0; k0 < DD; k0 += BKT) {
        bool has_next = (k0 + BKT < DD);
        if (has_next) {
            int kn = k0 + BKT;
#pragma unroll
            for (int p = 0; p < 2; p++)
                rA[p] = *(const uint4*)(g_xhi + (long)(mbase + ar[p]) * DD + kn + ac[p]);
            rB0 = *(const float4*)(F + (long)br_ld * DD + kn + bc_ld);
            rB1 = *(const float4*)(F + (long)br_ld * DD + kn + bc_ld + 4);
        }

        const __nv_bfloat16* Ah = smp + cur * STG;
        const __nv_bfloat16* Bh = Ah + BM * LDT;

#pragma unroll
        for (int ks = 0; ks < 2; ks++) {
            int kk = ks * 16;
            uint32_t ah[4][4], bh[2][2];
#pragma unroll
            for (int mt = 0; mt < 4; mt++)
                ldmat4(ah[mt], Ah + (arow + mt * 16) * LDT + kk + acolo);
            {
                uint32_t t4[4];
                ldmat4(t4, Bh + brow * LDT + kk + bcolo);
                bh[0][0] = t4[0]; bh[0][1] = t4[1];
                bh[1][0] = t4[2]; bh[1][1] = t4[3];
            }
#pragma unroll
            for (int mt = 0; mt < 4; mt++)
#pragma unroll
                for (int nt = 0; nt < 2; nt++)
                    mma16816(acc[mt][nt], ah[mt], bh[nt]);
        }

        if (has_next) {
            __nv_bfloat16* nAh = smp + (cur ^ 1) * STG;
            __nv_bfloat16* nBh = nAh + BM * LDT;
#pragma unroll
            for (int p = 0; p < 2; p++)
                *(uint4*)&nAh[ar[p] * LDT + ac[p]] = rA[p];
            *(uint4*)&nBh[br_ld * LDT + bc_ld] = cvt8(rB0, rB1);
            __syncthreads();
            cur ^= 1;
        }
    }
    __syncthreads();   // smem reuse for epilogue

    // ---- fused epilogue: per-row Σexp(L), Σ ct*L, Σ ct (this block's modality) ----
    float* s_e = (float*)smp;
    float* s_d = s_e + BM;
    float* s_c = s_e + 2 * BM;
    if (tid < BM) { s_e[tid] = 0.f; s_d[tid] = 0.f; s_c[tid] = 0.f; }
    __syncthreads();

    const int* pidArr = is_ir ? pi : pr;
    int cbase = jbase - (is_ir ? NRR : 0);
    int pidc[4];
#pragma unroll
    for (int nt = 0; nt < 2; nt++)
#pragma unroll
        for (int q = 0; q < 2; q++)
            pidc[nt * 2 + q] = pidArr[cbase + warp_n * 16 + nt * 8 + (lane & 3) * 2 + q];

    float esum[8], dsum[8], csum[8];
#pragma unroll
    for (int i = 0; i < 8; i++) { esum[i] = 0.f; dsum[i] = 0.f; csum[i] = 0.f; }

#pragma unroll
    for (int mt = 0; mt < 4; mt++)
#pragma unroll
        for (int nt = 0; nt < 2; nt++)
#pragma unroll
            for (int q = 0; q < 4; q++) {
                int hi = q >> 1;
                int ridx = mt * 2 + hi;
                int grow = mbase + warp_m * 64 + mt * 16 + hi * 8 + (lane >> 2);
                float L = acc[mt][nt][q] * kINV_TEMP;
                float e = __expf(L);
                float ct = CT[(long)grow * AA + pidc[nt * 2 + (q & 1)]];
                esum[ridx] += e;
                dsum[ridx] += ct * L;
                csum[ridx] += ct;
            }

#pragma unroll
    for (int i = 0; i < 8; i++) {
        float e = esum[i], d = dsum[i], c = csum[i];
        e += __shfl_xor_sync(0xFFFFFFFF, e, 1); e += __shfl_xor_sync(0xFFFFFFFF, e, 2);
        d += __shfl_xor_sync(0xFFFFFFFF, d, 1); d += __shfl_xor_sync(0xFFFFFFFF, d, 2);
        c += __shfl_xor_sync(0xFFFFFFFF, c, 1); c += __shfl_xor_sync(0xFFFFFFFF, c, 2);
        if ((lane & 3) == 0) {
            int rl = warp_m * 64 + (i >> 1) * 16 + (i & 1) * 8 + (lane >> 2);
            atomicAdd(&s_e[rl], e);
            atomicAdd(&s_d[rl], d);
            atomicAdd(&s_c[rl], c);
        }
    }
    __syncthreads();

    if (tid < BM) {
        int grow = mbase + tid;
        int m = is_ir ? 1 : 0;
        atomicAdd(&g_stats[grow * 6 + 0 + m], s_e[tid]);
        atomicAdd(&g_stats[grow * 6 + 2 + m], s_d[tid]);
        atomicAdd(&g_stats[grow * 6 + 4 + m], s_c[tid]);
    }
}

// ---------------------------------------------------------------- feature update (chains) + fused loss finalize
__global__ void k_update(const float* __restrict__ CT, const int* __restrict__ targets,
                         const int* __restrict__ pids_ir,
                         float* __restrict__ outF, float* __restrict__ d_out) {
    int i = blockIdx.x, t = threadIdx.x;

    if (i == BB) {       // loss finalize block
        const float* st = g_stats + t * 6;
        float er = st[0], ei = st[1], dr = st[2], di = st[3], cs = st[4], csi = st[5];
        float lyc = cs * logf(er) - dr;
        float ly  = cs * logf(2.0f * er) + csi * logf(2.0f * ei) - dr - di;
        __shared__ float r1[256], r2[256];
        r1[t] = lyc; r2[t] = ly;
        __syncthreads();
        for (int o = 128; o > 0; o >>= 1) {
            if (t < o) { r1[t] += r1[t + o]; r2[t] += r2[t + o]; }
            __syncthreads();
        }
        if (t == 0) {
            d_out[0] = r1[0] * (1.0f / BB);
            d_out[1] = r2[0] * (1.0f / BB);
        }
        return;
    }

    int tg = targets[i];
    for (int i2 = 0; i2 < i; i2++)
        if (targets[i2] == tg) return;        // not chain head
    int j = g_inv[tg];
    if (j < 0 || j >= NRR || pids_ir[j] != tg) return;  // validated inverse map

    __shared__ float red[256];
    float* row = outF + (long)j * DD;
    float f0 = row[t * 3 + 0];
    float f1 = row[t * 3 + 1];
    float f2 = row[t * 3 + 2];

    for (int s = i; s < BB; s++) {
        if (targets[s] != tg) continue;
        float yci = CT[(long)s * AA + tg];
        float m  = kMOM / fmaxf(yci, kMOM);
        float om = 1.0f - m;
        const float* xs = g_xnorm + (long)s * DD + t * 3;
        float u0 = m * f0 + om * xs[0];
        float u1 = m * f1 + om * xs[1];
        float u2 = m * f2 + om * xs[2];
        red[t] = u0 * u0 + u1 * u1 + u2 * u2;
        __syncthreads();
        for (int o = 128; o > 0; o >>= 1) { if (t < o) red[t] += red[t + o]; __syncthreads(); }
        float inv = rsqrtf(red[0]);
        __syncthreads();
        f0 = u0 * inv; f1 = u1 * inv; f2 = u2 * inv;
    }
    row[t * 3 + 0] = f0;
    row[t * 3 + 1] = f1;
    row[t * 3 + 2] = f2;
}

// ---------------------------------------------------------------- launch
extern "C" void kernel_launch(void* const* d_in, const int* in_sizes, int n_in,
                              void* d_out, int out_size) {
    const float* inputs  = (const float*)d_in[0];
    const int*   targets = (const int*)d_in[1];
    const float* CT      = (const float*)d_in[2];
    const float* Frgb    = (const float*)d_in[3];
    const float* Fir     = (const float*)d_in[4];
    const float* Fall    = (const float*)d_in[5];
    const int*   pr      = (const int*)d_in[6];
    const int*   pi      = (const int*)d_in[7];
    float* out = (float*)d_out;

    k_prep<<<BB, 256>>>(inputs, pi);
    dim3 gg(AA / BN, BB / BM);
    k_gemm_tc<<<gg, 256>>>(Frgb, Fir, CT, pr, pi);
    cudaMemcpyAsync(out + 2, Fall, (size_t)AA * DD * sizeof(float),
                    cudaMemcpyDeviceToDevice);
    k_update<<<BB + 1, 256>>>(CT, targets, pi, out + 2, out);
}